// round 8
// baseline (speedup 1.0000x reference)
#include <cuda_runtime.h>
#include <cuda_bf16.h>
#include <cstdint>

#define NTOK 16384
#define HDIM 4096
#define NEXP 64
#define BM   64
#define KC   32
#define STAGES 3
#define NCHUNK (HDIM / KC)          // 128
#define XS 36                        // x smem row stride (floats, 144B: 16B-aligned, 4-bank row shift)
#define WS 40                        // w smem row stride (bf16, 80B: 16B-aligned, 20-bank row shift)
#define X_STAGE (BM * XS)            // floats per stage
#define W_STAGE (NEXP * WS)          // bf16 per stage
#define SMEM_BYTES (STAGES * (X_STAGE * 4 + 2 * W_STAGE * 2))   // 3*(9216+10240) = 58368

#define FLT_MIN_NORMAL 1.17549435e-38f

// Pre-split W (fp32 -> bf16 hi + bf16 lo), 1 MB total, L2-resident.
__device__ __nv_bfloat16 g_w_hi[NEXP * HDIM];
__device__ __nv_bfloat16 g_w_lo[NEXP * HDIM];

__global__ void prep_w_kernel(const float* __restrict__ w) {
    int i = blockIdx.x * blockDim.x + threadIdx.x;
    if (i < NEXP * HDIM) {
        float v = w[i];
        __nv_bfloat16 hi = __float2bfloat16_rn(v);
        float r = v - __bfloat162float(hi);
        g_w_hi[i] = hi;
        g_w_lo[i] = __float2bfloat16_rn(r);
    }
}

__device__ __forceinline__ void mma_bf16(float* c, const uint32_t* a,
                                         uint32_t b0, uint32_t b1) {
    asm volatile(
        "mma.sync.aligned.m16n8k16.row.col.f32.bf16.bf16.f32 "
        "{%0,%1,%2,%3}, {%4,%5,%6,%7}, {%8,%9}, {%0,%1,%2,%3};\n"
        : "+f"(c[0]), "+f"(c[1]), "+f"(c[2]), "+f"(c[3])
        : "r"(a[0]), "r"(a[1]), "r"(a[2]), "r"(a[3]), "r"(b0), "r"(b1));
}

__device__ __forceinline__ void cvt_split(float2 f, uint32_t& hi, uint32_t& lo) {
    __nv_bfloat162 h = __floats2bfloat162_rn(f.x, f.y);
    float rx = f.x - __bfloat162float(h.x);
    float ry = f.y - __bfloat162float(h.y);
    __nv_bfloat162 l = __floats2bfloat162_rn(rx, ry);
    hi = *reinterpret_cast<uint32_t*>(&h);
    lo = *reinterpret_cast<uint32_t*>(&l);
}

__device__ __forceinline__ void cp16(void* smem_dst, const void* gmem_src) {
    uint32_t s = (uint32_t)__cvta_generic_to_shared(smem_dst);
    asm volatile("cp.async.cg.shared.global [%0], [%1], 16;\n" :: "r"(s), "l"(gmem_src));
}

// float -> monotone-sortable u32
__device__ __forceinline__ uint32_t f2sortable(float f) {
    uint32_t b = __float_as_uint(f);
    return b ^ (((int32_t)b >> 31) | 0x80000000u);
}
__device__ __forceinline__ float sortable2f(uint32_t k) {
    uint32_t b = (k & 0x80000000u) ? (k ^ 0x80000000u) : ~k;
    return __uint_as_float(b);
}

__global__ __launch_bounds__(128, 3)
void gate_kernel(const float* __restrict__ x,
                 const float* __restrict__ noise,
                 float* __restrict__ out) {
    extern __shared__ char smem[];
    float* xs = reinterpret_cast<float*>(smem);                                  // [STAGES][BM][XS]
    __nv_bfloat16* wh = reinterpret_cast<__nv_bfloat16*>(smem + STAGES * X_STAGE * 4); // [STAGES][NEXP][WS]
    __nv_bfloat16* wl = wh + STAGES * W_STAGE;

    const int tid  = threadIdx.x;
    const int warp = tid >> 5;    // 0..3
    const int lane = tid & 31;
    const int g    = lane >> 2;   // 0..7
    const int tg   = lane & 3;    // 0..3
    const int mBase = blockIdx.x * BM;

    float acc[8][4];
#pragma unroll
    for (int i = 0; i < 8; i++)
#pragma unroll
        for (int j = 0; j < 4; j++) acc[i][j] = 0.f;

    // issue one stage of cp.async loads (x tile + w hi/lo chunk) and commit
    auto issue_stage = [&](int c, int slot) {
        const int k0 = c * KC;
        float* xb = xs + slot * X_STAGE;
#pragma unroll
        for (int i = 0; i < 4; i++) {                 // 64 rows x 8 float4 = 512 granules
            int idx = tid + i * 128;
            int row = idx >> 3, c4 = idx & 7;
            cp16(xb + row * XS + c4 * 4,
                 x + (size_t)(mBase + row) * HDIM + k0 + c4 * 4);
        }
        __nv_bfloat16* whb = wh + slot * W_STAGE;
        __nv_bfloat16* wlb = wl + slot * W_STAGE;
#pragma unroll
        for (int i = 0; i < 2; i++) {                 // 64 rows x 4 granules = 256
            int idx = tid + i * 128;
            int row = idx >> 2, q = idx & 3;
            cp16(whb + row * WS + q * 8, g_w_hi + (size_t)row * HDIM + k0 + q * 8);
            cp16(wlb + row * WS + q * 8, g_w_lo + (size_t)row * HDIM + k0 + q * 8);
        }
        asm volatile("cp.async.commit_group;\n" ::: "memory");
    };

    // prologue: stages for chunks 0..STAGES-2
    issue_stage(0, 0);
    issue_stage(1, 1);

    for (int c = 0; c < NCHUNK; c++) {
        asm volatile("cp.async.wait_group %0;\n" :: "n"(STAGES - 2) : "memory");
        __syncthreads();   // chunk c visible to all; slot of chunk c-1 free for reuse

        if (c + STAGES - 1 < NCHUNK)
            issue_stage(c + STAGES - 1, (c + STAGES - 1) % STAGES);
        else
            asm volatile("cp.async.commit_group;\n" ::: "memory");  // keep group count uniform

        const int slot = c % STAGES;
        const float* xb = xs + slot * X_STAGE + warp * 16 * XS;
        const __nv_bfloat16* whb = wh + slot * W_STAGE;
        const __nv_bfloat16* wlb = wl + slot * W_STAGE;

#pragma unroll
        for (int ks = 0; ks < KC / 16; ks++) {
            const int k0 = ks * 16;
            float2 f00 = *reinterpret_cast<const float2*>(xb + g * XS + k0 + tg * 2);
            float2 f01 = *reinterpret_cast<const float2*>(xb + g * XS + k0 + tg * 2 + 8);
            float2 f10 = *reinterpret_cast<const float2*>(xb + (g + 8) * XS + k0 + tg * 2);
            float2 f11 = *reinterpret_cast<const float2*>(xb + (g + 8) * XS + k0 + tg * 2 + 8);
            uint32_t ah[4], al[4];
            cvt_split(f00, ah[0], al[0]);
            cvt_split(f10, ah[1], al[1]);
            cvt_split(f01, ah[2], al[2]);
            cvt_split(f11, ah[3], al[3]);
#pragma unroll
            for (int nt = 0; nt < 8; nt++) {
                const int e = nt * 8 + g;
                uint32_t bh0 = *reinterpret_cast<const uint32_t*>(whb + e * WS + k0 + tg * 2);
                uint32_t bh1 = *reinterpret_cast<const uint32_t*>(whb + e * WS + k0 + tg * 2 + 8);
                uint32_t bl0 = *reinterpret_cast<const uint32_t*>(wlb + e * WS + k0 + tg * 2);
                uint32_t bl1 = *reinterpret_cast<const uint32_t*>(wlb + e * WS + k0 + tg * 2 + 8);
                mma_bf16(acc[nt], ah, bh0, bh1);   // hi*hi
                mma_bf16(acc[nt], ah, bl0, bl1);   // hi*lo
                mma_bf16(acc[nt], al, bh0, bh1);   // lo*hi
            }
        }
    }

    // ---- epilogue: noise add, then FTZ/DAZ softmax semantics (XLA:CPU runs
    //      under ScopedFlushDenormal): score flushes to exactly 0 when
    //      fl(exp(d))/s is subnormal, i.e. exp(d) < FLT_MIN * s. Flushed
    //      experts tie at 0 -> lowest index wins (jax top_k). Above the flush
    //      line score order == order of d.
    const int n0 = mBase + warp * 16 + g;
    const int n1 = n0 + 8;
#pragma unroll
    for (int nt = 0; nt < 8; nt++) {
        const int e = nt * 8 + tg * 2;
        float2 nz0 = *reinterpret_cast<const float2*>(noise + (size_t)n0 * NEXP + e);
        float2 nz1 = *reinterpret_cast<const float2*>(noise + (size_t)n1 * NEXP + e);
        acc[nt][0] += nz0.x; acc[nt][1] += nz0.y;
        acc[nt][2] += nz1.x; acc[nt][3] += nz1.y;
    }

#pragma unroll
    for (int r = 0; r < 2; r++) {
        float m = -3.4e38f;
#pragma unroll
        for (int nt = 0; nt < 8; nt++) {
#pragma unroll
            for (int jj = 0; jj < 2; jj++)
                m = fmaxf(m, acc[nt][r * 2 + jj]);
        }
#pragma unroll
        for (int mm = 1; mm <= 2; mm <<= 1)
            m = fmaxf(m, __shfl_xor_sync(0xffffffffu, m, mm));

        float dv[16];
        float s = 0.f;
#pragma unroll
        for (int nt = 0; nt < 8; nt++) {
#pragma unroll
            for (int jj = 0; jj < 2; jj++) {
                float d = acc[nt][r * 2 + jj] - m;
                dv[nt * 2 + jj] = d;
                s += __expf(d);
            }
        }
#pragma unroll
        for (int mm = 1; mm <= 2; mm <<= 1)
            s += __shfl_xor_sync(0xffffffffu, s, mm);

        const float flushLim = FLT_MIN_NORMAL * s;

        unsigned long long k1 = 0ull, k2 = 0ull;
#pragma unroll
        for (int nt = 0; nt < 8; nt++) {
#pragma unroll
            for (int jj = 0; jj < 2; jj++) {
                float d = dv[nt * 2 + jj];
                int   e = nt * 8 + tg * 2 + jj;
                float ed = __expf(d);
                uint32_t k32 = (ed < flushLim) ? 0u : f2sortable(d);
                unsigned long long key =
                    ((unsigned long long)k32 << 32) | (unsigned long long)(64 - e);
                if (key > k1) { k2 = k1; k1 = key; }
                else if (key > k2) { k2 = key; }
            }
        }
#pragma unroll
        for (int mm = 1; mm <= 2; mm <<= 1) {
            unsigned long long o1 = __shfl_xor_sync(0xffffffffu, k1, mm);
            unsigned long long o2 = __shfl_xor_sync(0xffffffffu, k2, mm);
            if (o1 > k1) { k2 = k1; k1 = o1; } else if (o1 > k2) { k2 = o1; }
            if (o2 > k1) { k2 = k1; k1 = o2; } else if (o2 > k2) { k2 = o2; }
        }

        if (tg == 0) {
            const int n = (r == 0) ? n0 : n1;
            int i1 = 64 - (int)(k1 & 0xffffffffull);
            int i2 = 64 - (int)(k2 & 0xffffffffull);
            uint32_t k32_1 = (uint32_t)(k1 >> 32);
            uint32_t k32_2 = (uint32_t)(k2 >> 32);
            float inv = 1.0f / s;
            float w1 = (k32_1 == 0u) ? 0.f : __expf(sortable2f(k32_1)) * inv;
            float w2 = (k32_2 == 0u) ? 0.f : __expf(sortable2f(k32_2)) * inv;
            out[2 * n + 0] = (float)i1;
            out[2 * n + 1] = (float)i2;
            out[2 * NTOK + 2 * n + 0] = w1;
            out[2 * NTOK + 2 * n + 1] = w2;
        }
    }
}

extern "C" void kernel_launch(void* const* d_in, const int* in_sizes, int n_in,
                              void* d_out, int out_size) {
    const float* x     = (const float*)d_in[0];  // hidden_states [4,4096,4096]
    const float* w     = (const float*)d_in[1];  // weight [64,4096]
    const float* noise = (const float*)d_in[2];  // noise [16384,64]
    float* out = (float*)d_out;

    cudaFuncSetAttribute(gate_kernel,
                         cudaFuncAttributeMaxDynamicSharedMemorySize, SMEM_BYTES);

    prep_w_kernel<<<(NEXP * HDIM + 255) / 256, 256>>>(w);
    gate_kernel<<<NTOK / BM, 128, SMEM_BYTES>>>(x, noise, out);
}